// round 1
// baseline (speedup 1.0000x reference)
#include <cuda_runtime.h>
#include <cstdint>

// Problem constants
#define BATCH 8
#define CIN   128
#define COUTC 128
#define NSEL  8
#define HDIM  128
#define WDIM  128
#define HWP   (HDIM * WDIM)        // 16384
#define NPIX  (BATCH * HWP)        // 131072
#define KTOT  (CIN * 9)            // 1152
#define PX_TILE 128
#define KC      8
#define KTILES  (KTOT / KC)        // 144
#define INVALID_PIX 0xFFFFFFFFu

// ---- scratch (no allocations allowed) ----
__device__ unsigned int g_count[NSEL];
__device__ unsigned int g_list[NSEL][NPIX];                 // 4 MB
__device__ __align__(16) float g_wr[NSEL * KTOT * COUTC];   // 4.7 MB, [s][kk][co]

// ---- packed f32x2 helpers (Blackwell) ----
#define PACK2(d, lo, hi) asm("mov.b64 %0, {%1, %2};" : "=l"(d) : "f"(lo), "f"(hi))
#define UNPACK2(lo, hi, d) asm("mov.b64 {%0, %1}, %2;" : "=f"(lo), "=f"(hi) : "l"(d))
#define FMA2(d, a, b) asm("fma.rn.f32x2 %0, %1, %2, %0;" : "+l"(d) : "l"(a), "l"(b))

// ---------------------------------------------------------------------------
// Kernel 0: reset branch counters (must happen every launch / graph replay)
// ---------------------------------------------------------------------------
__global__ void reset_kernel() {
    if (threadIdx.x < NSEL) g_count[threadIdx.x] = 0u;
}

// ---------------------------------------------------------------------------
// Kernel 1: repack weight [co][ci][s][kh][kw] -> g_wr[s][ci*9+r][co]
// so that a (K-chunk x 128co) weight tile is a contiguous float4-able block.
// ---------------------------------------------------------------------------
__global__ void reorg_kernel(const float* __restrict__ w) {
    int t = blockIdx.x * blockDim.x + threadIdx.x;     // exactly NSEL*KTOT*COUTC threads
    int co   = t & (COUTC - 1);
    int rest = t >> 7;
    int kk   = rest % KTOT;
    int s    = rest / KTOT;
    int ci = kk / 9;
    int r  = kk - ci * 9;                              // kh*3+kw
    g_wr[t] = w[(((size_t)co * CIN + ci) * NSEL + s) * 9 + r];
}

// ---------------------------------------------------------------------------
// Kernel 2: argmax gate + grouped scatter (CTA-local histogram + rank)
// softmax is monotone and the renorm is a no-op -> argmax(selector) directly.
// jnp.argmax keeps the FIRST max -> strict '>' comparison.
// ---------------------------------------------------------------------------
__global__ void sel_scatter_kernel(const float* __restrict__ selector) {
    __shared__ unsigned int hist[NSEL];
    __shared__ unsigned int base[NSEL];
    int tid = threadIdx.x;
    if (tid < NSEL) hist[tid] = 0u;
    __syncthreads();

    int p  = blockIdx.x * 256 + tid;                   // 0 .. NPIX-1
    int b  = p >> 14;
    int hw = p & (HWP - 1);
    const float* sp = selector + (size_t)b * NSEL * HWP + hw;
    float best = sp[0];
    int bs = 0;
#pragma unroll
    for (int s = 1; s < NSEL; s++) {
        float v = sp[(size_t)s * HWP];
        if (v > best) { best = v; bs = s; }
    }
    unsigned int rank = atomicAdd(&hist[bs], 1u);
    __syncthreads();
    if (tid < NSEL) base[tid] = atomicAdd(&g_count[tid], hist[tid]);
    __syncthreads();
    g_list[bs][base[bs] + rank] = (unsigned int)p;
}

// ---------------------------------------------------------------------------
// Kernel 3: per-branch implicit-GEMM conv.
//   CTA = (pixel tile of 128, branch s). N = 128 couts, K = 1152.
//   As[kc][128px] gathered im2col from input; Bs[kc][128co] contiguous.
//   256 threads, each computes an 8px x 8co register tile with fma.rn.f32x2.
// ---------------------------------------------------------------------------
__global__ void __launch_bounds__(256, 2)
conv_kernel(const float* __restrict__ input,
            const float* __restrict__ bias,
            float* __restrict__ out) {
    const int s = blockIdx.y;
    const int tile0 = blockIdx.x * PX_TILE;
    const unsigned int cnt = g_count[s];
    if (tile0 >= (int)cnt) return;

    __shared__ __align__(16) float As[KC][PX_TILE];
    __shared__ __align__(16) float Bs[KC][COUTC];
    __shared__ unsigned int spix[PX_TILE];

    const int tid = threadIdx.x;

    if (tid < PX_TILE) {
        int idx = tile0 + tid;
        spix[tid] = (idx < (int)cnt) ? g_list[s][idx] : INVALID_PIX;
    }
    __syncthreads();

    // gather assignment: thread covers pixel (tid&127), K-half (tid>>7)
    const int gpx   = tid & 127;
    const int ghalf = tid >> 7;
    const unsigned int gp = spix[gpx];
    const bool gvalid = (gp != INVALID_PIX);
    int gb = 0, gh = 0, gw = 0;
    if (gvalid) { gb = gp >> 14; gh = (gp >> 7) & 127; gw = gp & 127; }
    const float* inb = input + (size_t)gb * CIN * HWP;

    // compute assignment: 8 couts x 8 pixels
    const int tco = (tid & 15) * 8;
    const int tpx = (tid >> 4) * 8;

    unsigned long long acc[8][4];
#pragma unroll
    for (int i = 0; i < 8; i++)
#pragma unroll
        for (int j = 0; j < 4; j++) acc[i][j] = 0ull;   // (0.f, 0.f)

    const float* wbase = g_wr + (size_t)s * KTOT * COUTC;

    for (int kt = 0; kt < KTILES; kt++) {
        __syncthreads();   // protect previous-iter smem reads

        // Bs: 8*128 contiguous floats for this K-chunk
        reinterpret_cast<float4*>(Bs)[tid] =
            reinterpret_cast<const float4*>(wbase + (size_t)kt * KC * COUTC)[tid];

        // As: gathered im2col (4 K-elements for one pixel per thread)
        {
            const int kkbase = kt * KC + ghalf * 4;
            float va[4];
#pragma unroll
            for (int j = 0; j < 4; j++) {
                int kk = kkbase + j;
                int ci = kk / 9;
                int r  = kk - ci * 9;
                int kh = r / 3;
                int kw = r - kh * 3;
                float v = 0.f;
                if (gvalid) {
                    int hh = gh + kh - 1;
                    int ww = gw + kw - 1;
                    if ((unsigned)hh < (unsigned)HDIM && (unsigned)ww < (unsigned)WDIM)
                        v = inb[((size_t)ci * HDIM + hh) * WDIM + ww];
                }
                va[j] = v;
            }
#pragma unroll
            for (int j = 0; j < 4; j++) As[ghalf * 4 + j][gpx] = va[j];
        }
        __syncthreads();

#pragma unroll
        for (int k = 0; k < KC; k++) {
            float4 a0 = *reinterpret_cast<const float4*>(&As[k][tpx]);
            float4 a1 = *reinterpret_cast<const float4*>(&As[k][tpx + 4]);
            float4 b0 = *reinterpret_cast<const float4*>(&Bs[k][tco]);
            float4 b1 = *reinterpret_cast<const float4*>(&Bs[k][tco + 4]);
            unsigned long long bb0, bb1, bb2, bb3;
            PACK2(bb0, b0.x, b0.y); PACK2(bb1, b0.z, b0.w);
            PACK2(bb2, b1.x, b1.y); PACK2(bb3, b1.z, b1.w);
            float av[8] = {a0.x, a0.y, a0.z, a0.w, a1.x, a1.y, a1.z, a1.w};
#pragma unroll
            for (int i = 0; i < 8; i++) {
                unsigned long long aa;
                PACK2(aa, av[i], av[i]);
                FMA2(acc[i][0], aa, bb0);
                FMA2(acc[i][1], aa, bb1);
                FMA2(acc[i][2], aa, bb2);
                FMA2(acc[i][3], aa, bb3);
            }
        }
    }

    // epilogue: bias + scattered store out[b][co][h][w]
    float bv[8];
#pragma unroll
    for (int j = 0; j < 8; j++) bv[j] = bias[tco + j];

#pragma unroll
    for (int i = 0; i < 8; i++) {
        unsigned int p = spix[tpx + i];
        if (p == INVALID_PIX) continue;
        int pb = p >> 14, ph = (p >> 7) & 127, pw = p & 127;
        float* op = out + (((size_t)pb * COUTC + tco) * HDIM + ph) * WDIM + pw;
#pragma unroll
        for (int j = 0; j < 4; j++) {
            float lo, hi;
            UNPACK2(lo, hi, acc[i][j]);
            op[(size_t)(2 * j) * HWP]     = lo + bv[2 * j];
            op[(size_t)(2 * j + 1) * HWP] = hi + bv[2 * j + 1];
        }
    }
}

// ---------------------------------------------------------------------------
extern "C" void kernel_launch(void* const* d_in, const int* in_sizes, int n_in,
                              void* d_out, int out_size) {
    const float* input    = (const float*)d_in[0];   // [8,128,128,128]
    const float* selector = (const float*)d_in[1];   // [8,8,128,128]
    const float* weight   = (const float*)d_in[2];   // [128,128,8,3,3]
    const float* bias     = (const float*)d_in[3];   // [128]
    float* out = (float*)d_out;                      // [8,128,128,128]

    reset_kernel<<<1, 32>>>();
    reorg_kernel<<<(NSEL * KTOT * COUTC) / 256, 256>>>(weight);
    sel_scatter_kernel<<<NPIX / 256, 256>>>(selector);
    conv_kernel<<<dim3(NPIX / PX_TILE, NSEL), 256>>>(input, bias, out);
}

// round 3
// speedup vs baseline: 2.4027x; 2.4027x over previous
#include <cuda_runtime.h>
#include <cstdint>

// ---------------- problem constants ----------------
#define NSEL   8
#define CIN    128
#define COUTC  128
#define HDIM   128
#define WDIM   128
#define HWP    16384            // HDIM*WDIM
#define NPIX   131072           // 8*HWP
#define KTOT   1152             // CIN*9
#define KC     16               // K per ktile
#define NKT    (KTOT / KC)      // 72
#define PX_TILE 128
#define INVALID_PIX 0xFFFFFFFFu

// padded smem row strides (floats)
#define KCP 20                  // A: [128 px][KCP]
#define BSP 132                 // B: [KC][BSP]
#define A_BUF_F (PX_TILE * KCP)         // 2560 floats = 10240 B
#define B_BUF_F (KC * BSP)              // 2112 floats =  8448 B
#define SMEM_BYTES (2*A_BUF_F*4 + 2*B_BUF_F*4 + 512)   // 37888 + spix

// ---------------- scratch (static device; no allocs) ----------------
__device__ unsigned int g_count[NSEL];
__device__ unsigned int g_list[NSEL][NPIX];                   // 4 MB
__device__ __align__(16) unsigned int g_wr[NSEL * KTOT * COUTC]; // tf32 bits, [s][kk][co]

// ---------------- PTX helpers ----------------
static __device__ __forceinline__ uint32_t smem_u32(const void* p) {
    uint32_t a;
    asm("{ .reg .u64 t; cvta.to.shared.u64 t, %1; cvt.u32.u64 %0, t; }" : "=r"(a) : "l"(p));
    return a;
}
static __device__ __forceinline__ uint32_t f2tf32(float v) {
    uint32_t u; asm("cvt.rna.tf32.f32 %0, %1;" : "=r"(u) : "f"(v)); return u;
}
#define CP_ASYNC16(dst, src) \
    asm volatile("cp.async.cg.shared.global [%0], [%1], 16;" :: "r"(dst), "l"(src))
#define CP_COMMIT() asm volatile("cp.async.commit_group;" ::: "memory")
#define CP_WAIT0()  asm volatile("cp.async.wait_group 0;" ::: "memory")

static __device__ __forceinline__ void mma_tf32(float c[4], const uint32_t a[4], const uint32_t b[2]) {
    asm volatile(
        "mma.sync.aligned.m16n8k8.row.col.f32.tf32.tf32.f32 "
        "{%0,%1,%2,%3}, {%4,%5,%6,%7}, {%8,%9}, {%0,%1,%2,%3};"
        : "+f"(c[0]), "+f"(c[1]), "+f"(c[2]), "+f"(c[3])
        : "r"(a[0]), "r"(a[1]), "r"(a[2]), "r"(a[3]), "r"(b[0]), "r"(b[1]));
}

// ---------------------------------------------------------------------------
// Kernel 0: reset branch counters
// ---------------------------------------------------------------------------
__global__ void reset_kernel() {
    if (threadIdx.x < NSEL) g_count[threadIdx.x] = 0u;
}

// ---------------------------------------------------------------------------
// Kernel 1: weight repack [co][ci][s][kh][kw] -> g_wr[s][kk][co] as tf32(rna)
// ---------------------------------------------------------------------------
__global__ void reorg_kernel(const float* __restrict__ w) {
    int t = blockIdx.x * blockDim.x + threadIdx.x;   // NSEL*KTOT*COUTC threads
    int co   = t & (COUTC - 1);
    int rest = t >> 7;
    int kk   = rest % KTOT;
    int s    = rest / KTOT;
    int ci = kk / 9;
    int r  = kk - ci * 9;
    g_wr[t] = f2tf32(w[(((size_t)co * CIN + ci) * NSEL + s) * 9 + r]);
}

// ---------------------------------------------------------------------------
// Kernel 2: argmax gate + grouped scatter (per-CTA histogram, 1 atomic/bin)
// ---------------------------------------------------------------------------
__global__ void sel_scatter_kernel(const float* __restrict__ selector) {
    __shared__ unsigned int hist[NSEL];
    __shared__ unsigned int base[NSEL];
    int tid = threadIdx.x;
    if (tid < NSEL) hist[tid] = 0u;
    __syncthreads();

    int p  = blockIdx.x * 256 + tid;
    int b  = p >> 14;
    int hw = p & (HWP - 1);
    const float* sp = selector + (size_t)b * NSEL * HWP + hw;
    float best = sp[0];
    int bs = 0;
#pragma unroll
    for (int s = 1; s < NSEL; s++) {
        float v = sp[(size_t)s * HWP];
        if (v > best) { best = v; bs = s; }
    }
    unsigned int rank = atomicAdd(&hist[bs], 1u);
    __syncthreads();
    if (tid < NSEL) base[tid] = atomicAdd(&g_count[tid], hist[tid]);
    __syncthreads();
    g_list[bs][base[bs] + rank] = (unsigned int)p;
}

// ---------------------------------------------------------------------------
// Kernel 3: grouped implicit-GEMM conv, tf32 mma.sync (m16n8k8).
//   CTA: 128 px (M) x 128 co (N), K=1152 in 72 chunks of 16.
//   8 warps as 2(M) x 4(N): warp tile 64px x 32co -> 4x4 mma frags per k8.
//   Double-buffered smem; A gathered (im2col) via register staging,
//   B via cp.async from L2-resident repacked weights.
// ---------------------------------------------------------------------------
__global__ void __launch_bounds__(256, 2)
conv_kernel(const float* __restrict__ input,
            const float* __restrict__ bias,
            float* __restrict__ out) {
    const int s = blockIdx.y;
    const unsigned int cnt = g_count[s];
    const int tile0 = blockIdx.x * PX_TILE;
    if (tile0 >= (int)cnt) return;

    extern __shared__ char dsm[];
    uint32_t* Asm = (uint32_t*)dsm;                          // 2 x A_BUF_F
    uint32_t* Bsm = (uint32_t*)(dsm + 2 * A_BUF_F * 4);      // 2 x B_BUF_F
    unsigned int* spix = (unsigned int*)(dsm + 2 * A_BUF_F * 4 + 2 * B_BUF_F * 4);
    const uint32_t bsmAddr = smem_u32(Bsm);

    const int tid  = threadIdx.x;
    const int wid  = tid >> 5;
    const int lane = tid & 31;

    if (tid < PX_TILE) {
        int idx = tile0 + tid;
        spix[tid] = (idx < (int)cnt) ? g_list[s][idx] : INVALID_PIX;
    }
    __syncthreads();

    // ---- gather assignment: 1 pixel x 8 K-elems (khalf) per ktile ----
    const int gpx   = tid >> 1;
    const int khalf = tid & 1;
    const unsigned int gp = spix[gpx];
    const bool gvalid = (gp != INVALID_PIX);
    const int gh = (gp >> 7) & 127, gw = gp & 127;
    const float* cbase = input + ((size_t)(gp >> 14) * CIN) * HWP + gh * WDIM + gw;

    // ---- compute assignment ----
    const int wm = wid & 1;            // M half (64 px)
    const int wn = wid >> 1;           // N quarter (32 co)
    const int mbase = wm * 64 + (lane >> 2);
    const int nbase = wn * 32 + (lane >> 2);
    const int kq    = lane & 3;

    float acc[4][4][4];
#pragma unroll
    for (int i = 0; i < 4; i++)
#pragma unroll
        for (int j = 0; j < 4; j++)
#pragma unroll
            for (int e = 0; e < 4; e++) acc[i][j][e] = 0.f;

    const unsigned int* wsrc = g_wr + (size_t)s * KTOT * COUTC;

    // ---------- fill helpers (inline) ----------
    // A gather for ktile kt into regs u[8] (tf32 bits)
    uint32_t u[8];
    auto gatherA = [&](int kt) {
        int kk = kt * KC + khalf * 8;
        int ci = kk / 9;
        int r  = kk - ci * 9;
        int kh = r / 3;
        int kw = r - kh * 3;
#pragma unroll
        for (int i = 0; i < 8; i++) {
            float f = 0.f;
            int y = gh + kh - 1, x = gw + kw - 1;
            if (gvalid && (unsigned)y < 128u && (unsigned)x < 128u)
                f = __ldg(cbase + ci * HWP + (kh - 1) * WDIM + (kw - 1));
            u[i] = f2tf32(f);
            kw++;
            if (kw == 3) { kw = 0; kh++; if (kh == 3) { kh = 0; ci++; } }
        }
    };
    auto stsA = [&](int buf) {
        uint32_t* dst = Asm + buf * A_BUF_F + gpx * KCP + khalf * 8;
        uint4* d4 = (uint4*)dst;
        d4[0] = make_uint4(u[0], u[1], u[2], u[3]);
        d4[1] = make_uint4(u[4], u[5], u[6], u[7]);
    };
    auto fillB = [&](int kt, int buf) {
        const char* src = (const char*)(wsrc + (size_t)kt * KC * COUTC);
#pragma unroll
        for (int c = tid; c < 512; c += 256) {
            int k = c >> 5, co4 = c & 31;
            uint32_t dst = bsmAddr + buf * (B_BUF_F * 4) + k * (BSP * 4) + co4 * 16;
            CP_ASYNC16(dst, src + c * 16);
        }
    };
    auto compute = [&](int buf) {
        const uint32_t* A = Asm + buf * A_BUF_F;
        const uint32_t* B = Bsm + buf * B_BUF_F;
#pragma unroll
        for (int step = 0; step < 2; step++) {
            const int k0 = step * 8;
            uint32_t af[4][4];
#pragma unroll
            for (int i = 0; i < 4; i++) {
                const uint32_t* ar = A + (mbase + i * 16) * KCP + k0 + kq;
                af[i][0] = ar[0];
                af[i][1] = ar[8 * KCP];
                af[i][2] = ar[4];
                af[i][3] = ar[8 * KCP + 4];
            }
#pragma unroll
            for (int j = 0; j < 4; j++) {
                uint32_t bf[2];
                const uint32_t* br = B + (k0 + kq) * BSP + nbase + j * 8;
                bf[0] = br[0];
                bf[1] = br[4 * BSP];
#pragma unroll
                for (int i = 0; i < 4; i++) mma_tf32(acc[i][j], af[i], bf);
            }
        }
    };

    // ---------- prologue: fill buffer 0 ----------
    gatherA(0);
    stsA(0);
    fillB(0, 0);
    CP_COMMIT();
    CP_WAIT0();
    __syncthreads();

    // ---------- main loop: double buffered ----------
    for (int kt = 0; kt < NKT; kt++) {
        const int cur = kt & 1, nxt = cur ^ 1;
        const bool more = (kt + 1 < NKT);
        if (more) {
            gatherA(kt + 1);          // LDGs overlap with MMA below
            fillB(kt + 1, nxt);
            CP_COMMIT();
        }
        compute(cur);
        if (more) {
            stsA(nxt);
            CP_WAIT0();
        }
        __syncthreads();
    }

    // ---------- epilogue: bias + scattered stores ----------
    float bv[4][2];
#pragma unroll
    for (int j = 0; j < 4; j++) {
        int co = wn * 32 + j * 8 + 2 * kq;
        bv[j][0] = __ldg(&bias[co]);
        bv[j][1] = __ldg(&bias[co + 1]);
    }
#pragma unroll
    for (int i = 0; i < 4; i++) {
        const int r0 = wm * 64 + i * 16 + (lane >> 2);
        const int r1 = r0 + 8;
        const unsigned int p0 = spix[r0];
        const unsigned int p1 = spix[r1];
#pragma unroll
        for (int half = 0; half < 2; half++) {
            const unsigned int p = half ? p1 : p0;
            if (p == INVALID_PIX) continue;
            const int pb = p >> 14;
            const int hw = p & (HWP - 1);
            float* ob = out + ((size_t)pb * COUTC) * HWP + hw;
#pragma unroll
            for (int j = 0; j < 4; j++) {
                const int co = wn * 32 + j * 8 + 2 * kq;
                ob[(size_t)co * HWP]       = acc[i][j][half * 2]     + bv[j][0];
                ob[(size_t)(co + 1) * HWP] = acc[i][j][half * 2 + 1] + bv[j][1];
            }
        }
    }
}

// ---------------------------------------------------------------------------
extern "C" void kernel_launch(void* const* d_in, const int* in_sizes, int n_in,
                              void* d_out, int out_size) {
    const float* input    = (const float*)d_in[0];   // [8,128,128,128]
    const float* selector = (const float*)d_in[1];   // [8,8,128,128]
    const float* weight   = (const float*)d_in[2];   // [128,128,8,3,3]
    const float* bias     = (const float*)d_in[3];   // [128]
    float* out = (float*)d_out;                      // [8,128,128,128]

    static bool attr_done = false;
    if (!attr_done) {
        cudaFuncSetAttribute(conv_kernel, cudaFuncAttributeMaxDynamicSharedMemorySize, SMEM_BYTES);
        attr_done = true;
    }

    reset_kernel<<<1, 32>>>();
    reorg_kernel<<<(NSEL * KTOT * COUTC) / 256, 256>>>(weight);
    sel_scatter_kernel<<<NPIX / 256, 256>>>(selector);
    conv_kernel<<<dim3(NPIX / PX_TILE, NSEL), 256, SMEM_BYTES>>>(input, bias, out);
}

// round 4
// speedup vs baseline: 2.7772x; 1.1559x over previous
#include <cuda_runtime.h>
#include <cstdint>

// ---------------- problem constants ----------------
#define NSEL   8
#define CIN    128
#define COUTC  128
#define HDIM   128
#define WDIM   128
#define HWP    16384            // HDIM*WDIM
#define NPIX   131072           // 8*HWP
#define KTOT   1152             // CIN*9
#define KC     32               // K per ktile
#define NKT    36               // KTOT/KC
#define PX_TILE 128
#define NBLK   512              // NPIX/256
#define INVALID_PIX 0xFFFFFFFFu

// smem: A frags 2x16KB | B frags 2x16KB | spix 512B
#define AFRAG_B 16384
#define BFRAG_B 16384
#define SMEM_BYTES (2*AFRAG_B + 2*BFRAG_B + 512)

// ---------------- scratch (static device; no allocs) ----------------
__device__ unsigned int  g_count[NSEL];
__device__ unsigned int  g_list[NSEL][NPIX];                    // 4 MB
__device__ unsigned char g_bs[NPIX];
__device__ unsigned int  g_bhist[NBLK][NSEL];
__device__ unsigned int  g_bbase[NBLK][NSEL];
__device__ __align__(16) unsigned int g_wb[NSEL * NKT * 4096];  // frag-order tf32 B tiles

// ---------------- PTX helpers ----------------
static __device__ __forceinline__ uint32_t smem_u32(const void* p) {
    uint32_t a;
    asm("{ .reg .u64 t; cvta.to.shared.u64 t, %1; cvt.u32.u64 %0, t; }" : "=r"(a) : "l"(p));
    return a;
}
static __device__ __forceinline__ uint32_t f2tf32(float v) {
    uint32_t u; asm("cvt.rna.tf32.f32 %0, %1;" : "=r"(u) : "f"(v)); return u;
}
#define CP_ASYNC16(dst, src) \
    asm volatile("cp.async.cg.shared.global [%0], [%1], 16;" :: "r"(dst), "l"(src))
#define CP_COMMIT() asm volatile("cp.async.commit_group;" ::: "memory")
#define CP_WAIT0()  asm volatile("cp.async.wait_group 0;" ::: "memory")

#define LDS128(v, addr) \
    asm volatile("ld.shared.v4.b32 {%0,%1,%2,%3}, [%4];" \
        : "=r"((v)[0]), "=r"((v)[1]), "=r"((v)[2]), "=r"((v)[3]) : "r"(addr))
#define LDS64(v, addr) \
    asm volatile("ld.shared.v2.b32 {%0,%1}, [%2];" \
        : "=r"((v)[0]), "=r"((v)[1]) : "r"(addr))
#define STS64(addr, lo, hi) \
    asm volatile("st.shared.v2.b32 [%0], {%1,%2};" :: "r"(addr), "r"(lo), "r"(hi))

static __device__ __forceinline__ void mma_tf32(float c[4], uint32_t a0, uint32_t a1,
                                                uint32_t a2, uint32_t a3,
                                                uint32_t b0, uint32_t b1) {
    asm volatile(
        "mma.sync.aligned.m16n8k8.row.col.f32.tf32.tf32.f32 "
        "{%0,%1,%2,%3}, {%4,%5,%6,%7}, {%8,%9}, {%0,%1,%2,%3};"
        : "+f"(c[0]), "+f"(c[1]), "+f"(c[2]), "+f"(c[3])
        : "r"(a0), "r"(a1), "r"(a2), "r"(a3), "r"(b0), "r"(b1));
}

// ---------------------------------------------------------------------------
// Kernel 1: argmax gate + per-block histograms
// ---------------------------------------------------------------------------
__global__ void hist_kernel(const float* __restrict__ selector) {
    __shared__ unsigned int h[NSEL];
    int tid = threadIdx.x;
    if (tid < NSEL) h[tid] = 0u;
    __syncthreads();

    int p  = blockIdx.x * 256 + tid;
    int b  = p >> 14;
    int hw = p & (HWP - 1);
    const float* sp = selector + (size_t)b * NSEL * HWP + hw;
    float best = sp[0];
    int bs = 0;
#pragma unroll
    for (int s = 1; s < NSEL; s++) {
        float v = sp[(size_t)s * HWP];
        if (v > best) { best = v; bs = s; }
    }
    g_bs[p] = (unsigned char)bs;
    atomicAdd(&h[bs], 1u);
    __syncthreads();
    if (tid < NSEL) g_bhist[blockIdx.x][tid] = h[tid];
}

// ---------------------------------------------------------------------------
// Kernel 2: exclusive scan of block histograms per bin (1 CTA)
// ---------------------------------------------------------------------------
__global__ void scan_kernel() {
    __shared__ unsigned int part[NSEL][32];
    int tid = threadIdx.x;
    int s = tid & 7, c = tid >> 3;       // c in [0,32)
    unsigned int sum = 0;
#pragma unroll
    for (int b = c * 16; b < c * 16 + 16; b++) sum += g_bhist[b][s];
    part[s][c] = sum;
    __syncthreads();
    if (tid < NSEL) {
        unsigned int run = 0;
#pragma unroll
        for (int c2 = 0; c2 < 32; c2++) {
            unsigned int t = part[tid][c2];
            part[tid][c2] = run;
            run += t;
        }
        g_count[tid] = run;
    }
    __syncthreads();
    unsigned int run = part[s][c];
    for (int b = c * 16; b < c * 16 + 16; b++) {
        g_bbase[b][s] = run;
        run += g_bhist[b][s];
    }
}

// ---------------------------------------------------------------------------
// Kernel 3: ordered scatter -> sorted per-bin pixel lists
// ---------------------------------------------------------------------------
__global__ void scatter_kernel() {
    __shared__ unsigned int wh[8][NSEL];
    int tid = threadIdx.x;
    int wid = tid >> 5;
    if (tid < 64) ((unsigned int*)wh)[tid] = 0u;
    __syncthreads();

    int p = blockIdx.x * 256 + tid;
    int bs = g_bs[p];
    unsigned int mask = __match_any_sync(0xFFFFFFFFu, bs);
    unsigned int lt   = (1u << (tid & 31)) - 1u;
    unsigned int rank = __popc(mask & lt);
    if (rank == 0) wh[wid][bs] = __popc(mask);
    __syncthreads();
    if (tid < NSEL) {
        unsigned int run = 0;
#pragma unroll
        for (int w = 0; w < 8; w++) {
            unsigned int t = wh[w][tid];
            wh[w][tid] = run;
            run += t;
        }
    }
    __syncthreads();
    unsigned int idx = g_bbase[blockIdx.x][bs] + wh[wid][bs] + rank;
    g_list[bs][idx] = (unsigned int)p;
}

// ---------------------------------------------------------------------------
// Kernel 4: weight repack -> fragment-order tf32 B tiles.
// Tile (s,kt) element e: e = ((j*4+t)*32 + lane)*2 + reg
//   co = j*8 + (lane>>2); kk = kt*32 + t*8 + reg*4 + (lane&3)
// ---------------------------------------------------------------------------
__global__ void reorg_kernel(const float* __restrict__ w) {
    int t = blockIdx.x * 256 + threadIdx.x;       // 8*36*4096 threads
    int e    = t & 4095;
    int tile = t >> 12;                           // s*36 + kt
    int kt = tile % NKT;
    int s  = tile / NKT;
    int reg  = e & 1;
    int lane = (e >> 1) & 31;
    int tt   = (e >> 6) & 3;
    int j    = e >> 8;
    int co = j * 8 + (lane >> 2);
    int kk = kt * 32 + tt * 8 + reg * 4 + (lane & 3);
    int ci = kk / 9;
    int r  = kk - ci * 9;
    g_wb[t] = f2tf32(w[(((size_t)co * CIN + ci) * NSEL + s) * 9 + r]);
}

// ---------------------------------------------------------------------------
// Kernel 5: grouped implicit-GEMM conv, tf32 mma.sync, frag-layout smem.
// ---------------------------------------------------------------------------
__global__ void __launch_bounds__(256, 2)
conv_kernel(const float* __restrict__ input,
            const float* __restrict__ bias,
            float* __restrict__ out) {
    const int s = blockIdx.y;
    const unsigned int cnt = g_count[s];
    const int tile0 = blockIdx.x * PX_TILE;
    if (tile0 >= (int)cnt) return;

    extern __shared__ char dsm[];
    const uint32_t Abase = smem_u32(dsm);
    const uint32_t Bbase = Abase + 2 * AFRAG_B;
    unsigned int* spix = (unsigned int*)(dsm + 2 * AFRAG_B + 2 * BFRAG_B);

    const int tid  = threadIdx.x;
    const int wid  = tid >> 5;
    const int lane = tid & 31;

    if (tid < PX_TILE) {
        int idx = tile0 + tid;
        spix[tid] = (idx < (int)cnt) ? g_list[s][idx] : INVALID_PIX;
    }
    __syncthreads();

    // ---- gather assignment: px = tid>>1, K half kg = tid&1 (16 kk each) ----
    const int gpx = tid >> 1;
    const int kg  = tid & 1;
    const unsigned int gp = spix[gpx];
    const bool gvalid = (gp != INVALID_PIX);
    const int gh = (gp >> 7) & 127, gw = gp & 127;
    const float* cbase = input + ((size_t)(gp >> 14) * CIN) * HWP + gh * WDIM + gw;
    const bool fast = gvalid && gh >= 1 && gh <= 126 && gw >= 1 && gw <= 126;
    // A-frag write base components
    const int i_px = gpx >> 4;
    const uint32_t hoff = ((gpx >> 3) & 1) * 8;
    const uint32_t slotbase = (uint32_t)((gpx & 7) << 2);

    // ---- compute assignment: 8 warps = 2(M) x 4(N) ----
    const int wm = wid & 1;
    const int wn = wid >> 1;
    const uint32_t slotr = (uint32_t)lane ^ (((uint32_t)lane >> 3) & 3u);

    float acc[4][4][4];
#pragma unroll
    for (int i = 0; i < 4; i++)
#pragma unroll
        for (int j = 0; j < 4; j++)
#pragma unroll
            for (int e = 0; e < 4; e++) acc[i][j][e] = 0.f;

    const unsigned int* wtiles = g_wb + (size_t)s * NKT * 4096;

    uint32_t u[8];

    // gather 8 taps (one k8 step) starting at kk0 into u (raw fp32 bits)
    auto ldg_half = [&](int kk0) {
        int ci = kk0 / 9;
        int r  = kk0 - ci * 9;
        int kh = (r * 11) >> 5;
        int kw = r - kh * 3;
        if (fast) {
            const float* ptr = cbase + ci * HWP + (kh - 1) * WDIM + (kw - 1);
#pragma unroll
            for (int i = 0; i < 8; i++) {
                u[i] = __float_as_uint(__ldg(ptr));
                kw++; ptr++;
                if (kw == 3) {
                    kw = 0; kh++; ptr += WDIM - 3;
                    if (kh == 3) { kh = 0; ci++; ptr += HWP - 3 * WDIM; }
                }
            }
        } else {
#pragma unroll
            for (int i = 0; i < 8; i++) {
                int y = gh + kh - 1, x = gw + kw - 1;
                float f = 0.f;
                if (gvalid && (unsigned)y < 128u && (unsigned)x < 128u)
                    f = __ldg(cbase + ci * HWP + (kh - 1) * WDIM + (kw - 1));
                u[i] = __float_as_uint(f);
                kw++;
                if (kw == 3) { kw = 0; kh++; if (kh == 3) { kh = 0; ci++; } }
            }
        }
    };

    // store u (8 taps = one k8 step t_abs) as A-frag pairs (tf32)
    auto sts_half = [&](int buf, int t_abs) {
        const uint32_t base = Abase + buf * AFRAG_B +
                              (uint32_t)((i_px * 4 + t_abs) * 32) * 16u + hoff;
#pragma unroll
        for (int kq = 0; kq < 4; kq++) {
            uint32_t slot = slotbase + (uint32_t)kq;
            slot ^= (slot >> 3) & 3u;
            STS64(base + slot * 16u, f2tf32(__uint_as_float(u[kq])),
                                     f2tf32(__uint_as_float(u[kq + 4])));
        }
    };

    auto fillB = [&](int kt, int buf) {
        const char* src = (const char*)(wtiles + (size_t)kt * 4096);
        const uint32_t dst = Bbase + buf * BFRAG_B;
#pragma unroll
        for (int i = 0; i < 4; i++)
            CP_ASYNC16(dst + (tid + 256 * i) * 16u, src + (tid + 256 * i) * 16);
    };

    // one k8 MMA step
    auto step = [&](int buf, int t) {
        const uint32_t Ab = Abase + buf * AFRAG_B;
        const uint32_t Bb = Bbase + buf * BFRAG_B;
        uint32_t av[4][4];
#pragma unroll
        for (int i = 0; i < 4; i++)
            LDS128(av[i], Ab + (uint32_t)((((wm * 4 + i) * 4 + t) * 32)) * 16u + slotr * 16u);
        uint32_t bv[4][2];
#pragma unroll
        for (int j = 0; j < 4; j++)
            LDS64(bv[j], Bb + (uint32_t)((((wn * 4 + j) * 4 + t) * 32 + lane)) * 8u);
#pragma unroll
        for (int j = 0; j < 4; j++)
#pragma unroll
            for (int i = 0; i < 4; i++)
                mma_tf32(acc[i][j], av[i][0], av[i][2], av[i][1], av[i][3],
                         bv[j][0], bv[j][1]);
    };

    // ---------- prologue: fill buffer 0 ----------
    fillB(0, 0);
    CP_COMMIT();
    ldg_half(kg * 16);
    sts_half(0, kg * 2);
    ldg_half(kg * 16 + 8);
    sts_half(0, kg * 2 + 1);
    CP_WAIT0();
    __syncthreads();

    // ---------- main loop ----------
    for (int kt = 0; kt < NKT; kt++) {
        const int cur = kt & 1, nxt = cur ^ 1;
        const bool more = (kt + 1 < NKT);
        const int kkn = (kt + 1) * KC + kg * 16;
        if (more) {
            fillB(kt + 1, nxt);
            CP_COMMIT();
            ldg_half(kkn);                 // LDGs in flight over compute
        }
        step(cur, 0);
        step(cur, 1);
        if (more) {
            sts_half(nxt, kg * 2);
            ldg_half(kkn + 8);
        }
        step(cur, 2);
        step(cur, 3);
        if (more) {
            sts_half(nxt, kg * 2 + 1);
            CP_WAIT0();
        }
        __syncthreads();
    }

    // ---------- epilogue: bias + scattered stores ----------
    const int kq = lane & 3;
    float bv[4][2];
#pragma unroll
    for (int j = 0; j < 4; j++) {
        int co = wn * 32 + j * 8 + 2 * kq;
        bv[j][0] = __ldg(&bias[co]);
        bv[j][1] = __ldg(&bias[co + 1]);
    }
#pragma unroll
    for (int i = 0; i < 4; i++) {
        const int r0 = wm * 64 + i * 16 + (lane >> 2);
#pragma unroll
        for (int half = 0; half < 2; half++) {
            const unsigned int p = spix[r0 + half * 8];
            if (p == INVALID_PIX) continue;
            const int pb = p >> 14;
            const int hw = p & (HWP - 1);
            float* ob = out + ((size_t)pb * COUTC) * HWP + hw;
#pragma unroll
            for (int j = 0; j < 4; j++) {
                const int co = wn * 32 + j * 8 + 2 * kq;
                ob[(size_t)co * HWP]       = acc[i][j][half * 2]     + bv[j][0];
                ob[(size_t)(co + 1) * HWP] = acc[i][j][half * 2 + 1] + bv[j][1];
            }
        }
    }
}

// ---------------------------------------------------------------------------
extern "C" void kernel_launch(void* const* d_in, const int* in_sizes, int n_in,
                              void* d_out, int out_size) {
    const float* input    = (const float*)d_in[0];   // [8,128,128,128]
    const float* selector = (const float*)d_in[1];   // [8,8,128,128]
    const float* weight   = (const float*)d_in[2];   // [128,128,8,3,3]
    const float* bias     = (const float*)d_in[3];   // [128]
    float* out = (float*)d_out;                      // [8,128,128,128]

    static bool attr_done = false;
    if (!attr_done) {
        cudaFuncSetAttribute(conv_kernel, cudaFuncAttributeMaxDynamicSharedMemorySize, SMEM_BYTES);
        attr_done = true;
    }

    hist_kernel<<<NBLK, 256>>>(selector);
    scan_kernel<<<1, 256>>>();
    scatter_kernel<<<NBLK, 256>>>();
    reorg_kernel<<<(NSEL * NKT * 4096) / 256, 256>>>(weight);
    conv_kernel<<<dim3(NPIX / PX_TILE, NSEL), 256, SMEM_BYTES>>>(input, bias, out);
}